// round 13
// baseline (speedup 1.0000x reference)
#include <cuda_runtime.h>
#include <cuda_bf16.h>
#include <cstdint>
#include <math.h>

#define B_   2
#define S_   2048
#define H_   16
#define DH_  64
#define DM_  1024
#define MTOK (B_ * S_)        // 4096

// ---------------- scratch (device-code references ONLY) ----------------
__device__ float g_qkv[(size_t)MTOK * 3 * DM_];     // 48 MB
__device__ float2 g_rope_tab[S_ * 32];              // cos/sin per (s, i)

// bf16 hi/lo GEMM operands
__device__ __nv_bfloat16 g_xh [(size_t)MTOK * DM_];
__device__ __nv_bfloat16 g_xl [(size_t)MTOK * DM_];
__device__ __nv_bfloat16 g_wqh[(size_t)3 * DM_ * DM_];
__device__ __nv_bfloat16 g_wql[(size_t)3 * DM_ * DM_];
__device__ __nv_bfloat16 g_woh[(size_t)DM_ * DM_];
__device__ __nv_bfloat16 g_wol[(size_t)DM_ * DM_];
__device__ __nv_bfloat16 g_aoh[(size_t)MTOK * DM_];
__device__ __nv_bfloat16 g_aol[(size_t)MTOK * DM_];

// bf16 hi/lo attention operands (Q has 0.125 score scale folded in)
__device__ __nv_bfloat16 g_qhi[(size_t)B_ * H_ * S_ * DH_];
__device__ __nv_bfloat16 g_qlo[(size_t)B_ * H_ * S_ * DH_];
__device__ __nv_bfloat16 g_khi[(size_t)B_ * H_ * S_ * DH_];
__device__ __nv_bfloat16 g_klo[(size_t)B_ * H_ * S_ * DH_];
__device__ __nv_bfloat16 g_vthi[(size_t)B_ * H_ * DH_ * S_];  // transposed [bh][d][s]
__device__ __nv_bfloat16 g_vtlo[(size_t)B_ * H_ * DH_ * S_];

// ---------------- helpers ----------------
__device__ __forceinline__ uint32_t smem_u32(const void* p) {
    uint32_t a;
    asm("{ .reg .u64 t; cvta.to.shared.u64 t, %1; cvt.u32.u64 %0, t; }"
        : "=r"(a) : "l"(p));
    return a;
}

__device__ __forceinline__ void mma16816(float* d, const uint32_t* a,
                                         uint32_t b0, uint32_t b1) {
    asm volatile(
        "mma.sync.aligned.m16n8k16.row.col.f32.bf16.bf16.f32 "
        "{%0,%1,%2,%3}, {%4,%5,%6,%7}, {%8,%9}, {%0,%1,%2,%3};"
        : "+f"(d[0]), "+f"(d[1]), "+f"(d[2]), "+f"(d[3])
        : "r"(a[0]), "r"(a[1]), "r"(a[2]), "r"(a[3]), "r"(b0), "r"(b1));
}

__device__ __forceinline__ void ldsm4(uint32_t& r0, uint32_t& r1,
                                      uint32_t& r2, uint32_t& r3, uint32_t addr) {
    asm volatile("ldmatrix.sync.aligned.m8n8.x4.shared.b16 {%0,%1,%2,%3}, [%4];"
                 : "=r"(r0), "=r"(r1), "=r"(r2), "=r"(r3) : "r"(addr));
}

__device__ __forceinline__ uint32_t pack_bf16(float x, float y) {
    __nv_bfloat162 t(__float2bfloat16(x), __float2bfloat16(y));
    return *(uint32_t*)&t;
}

// ---------------- fp32 -> bf16 hi/lo split (one-time, streaming) ----------
__global__ void __launch_bounds__(256) k_splitg(const float* __restrict__ in,
                                                int which)
{
    __nv_bfloat16 *hi, *lo;
    if      (which == 0) { hi = g_xh;  lo = g_xl;  }
    else if (which == 1) { hi = g_wqh; lo = g_wql; }
    else                 { hi = g_woh; lo = g_wol; }

    int i = (blockIdx.x * 256 + threadIdx.x) * 4;
    float4 v = *(const float4*)(in + i);
    __nv_bfloat16 h0 = __float2bfloat16(v.x);
    __nv_bfloat16 h1 = __float2bfloat16(v.y);
    __nv_bfloat16 h2 = __float2bfloat16(v.z);
    __nv_bfloat16 h3 = __float2bfloat16(v.w);
    *(__nv_bfloat162*)(hi + i)     = __nv_bfloat162(h0, h1);
    *(__nv_bfloat162*)(hi + i + 2) = __nv_bfloat162(h2, h3);
    *(__nv_bfloat162*)(lo + i)     = __nv_bfloat162(
        __float2bfloat16(v.x - __bfloat162float(h0)),
        __float2bfloat16(v.y - __bfloat162float(h1)));
    *(__nv_bfloat162*)(lo + i + 2) = __nv_bfloat162(
        __float2bfloat16(v.z - __bfloat162float(h2)),
        __float2bfloat16(v.w - __bfloat162float(h3)));
}

// ---------------- HMMA split-bf16 GEMM (R12-proven) ------------------------
// CTA tile 128x256, BK=16, double-buffered smem, 8 warps (2x4), warp 64x64.
#define LDT 24                         // halves per smem row (48 B stride)
#define A_TILE_H (128 * LDT)           // 3072 halves
#define B_TILE_H (256 * LDT)           // 6144 halves
#define BUF_H    (2 * A_TILE_H + 2 * B_TILE_H)   // 18432 halves
#define GEMM_SMEM_B (2 * BUF_H * 2)    // 73728 bytes

__device__ __forceinline__ void gemm_pre(const __nv_bfloat16* __restrict__ Ahi,
                                         const __nv_bfloat16* __restrict__ Alo,
                                         const __nv_bfloat16* __restrict__ Bhi,
                                         const __nv_bfloat16* __restrict__ Blo,
                                         float* __restrict__ C, int N)
{
    extern __shared__ __align__(16) __nv_bfloat16 sm[];
    const uint32_t sm0 = smem_u32(sm);

    const int tid  = threadIdx.x;
    const int lane = tid & 31;
    const int wid  = tid >> 5;
    const int wm   = wid & 1;
    const int wn   = wid >> 1;
    const int gid  = lane >> 2;
    const int tig  = lane & 3;
    const int bm   = blockIdx.y * 128;
    const int bn   = blockIdx.x * 256;

    const int lr   = lane & 7;
    const int qd   = lane >> 3;
    const int arow = (qd & 1) * 8 + lr;
    const int acol = (qd >> 1) * 8;
    const int brow = (qd >> 1) * 8 + lr;
    const int bcol = (qd & 1) * 8;

    const int rowA = tid >> 1;
    const int sgA  = tid & 1;

    float acc[4][8][4];
#pragma unroll
    for (int i = 0; i < 4; i++)
#pragma unroll
        for (int j = 0; j < 8; j++)
#pragma unroll
            for (int k = 0; k < 4; k++) acc[i][j][k] = 0.0f;

    uint4 pah, pal, pbh[2], pbl[2];

    auto fetch = [&](int c) {
        const int kk = c << 4;
        const int ke = kk + sgA * 8;
        pah = *(const uint4*)(Ahi + (size_t)(bm + rowA) * DM_ + ke);
        pal = *(const uint4*)(Alo + (size_t)(bm + rowA) * DM_ + ke);
#pragma unroll
        for (int i = 0; i < 2; i++) {
            const int idx = i * 256 + tid;
            const int rb  = idx >> 1;
            const int keb = kk + (idx & 1) * 8;
            pbh[i] = *(const uint4*)(Bhi + (size_t)(bn + rb) * DM_ + keb);
            pbl[i] = *(const uint4*)(Blo + (size_t)(bn + rb) * DM_ + keb);
        }
    };

    fetch(0);

    const int NC = DM_ / 16;
    for (int c = 0; c < NC; c++) {
        const int buf = c & 1;
        __nv_bfloat16* base = sm + buf * BUF_H;

        *(uint4*)&base[rowA * LDT + sgA * 8] = pah;
        *(uint4*)&base[A_TILE_H + rowA * LDT + sgA * 8] = pal;
#pragma unroll
        for (int i = 0; i < 2; i++) {
            const int idx = i * 256 + tid;
            const int rb  = idx >> 1;
            const int sg  = (idx & 1) * 8;
            *(uint4*)&base[2 * A_TILE_H + rb * LDT + sg] = pbh[i];
            *(uint4*)&base[2 * A_TILE_H + B_TILE_H + rb * LDT + sg] = pbl[i];
        }
        __syncthreads();

        if (c + 1 < NC) fetch(c + 1);

        const uint32_t bufb = sm0 + (uint32_t)buf * BUF_H * 2;

        uint32_t ah[4][4], al[4][4];
#pragma unroll
        for (int mi = 0; mi < 4; mi++) {
            const uint32_t aoff =
                (uint32_t)((wm * 64 + mi * 16 + arow) * LDT + acol) * 2;
            ldsm4(ah[mi][0], ah[mi][1], ah[mi][2], ah[mi][3], bufb + aoff);
            ldsm4(al[mi][0], al[mi][1], al[mi][2], al[mi][3],
                  bufb + A_TILE_H * 2 + aoff);
        }
#pragma unroll
        for (int pg = 0; pg < 4; pg++) {
            const uint32_t boff =
                (uint32_t)((wn * 64 + pg * 16 + brow) * LDT + bcol) * 2;
            uint32_t bh0, bh1, bh2, bh3, bl0, bl1, bl2, bl3;
            ldsm4(bh0, bh1, bh2, bh3, bufb + 4 * A_TILE_H + boff);
            ldsm4(bl0, bl1, bl2, bl3, bufb + 4 * A_TILE_H + B_TILE_H * 2 + boff);
            const int n0 = pg * 2, n1 = pg * 2 + 1;
#pragma unroll
            for (int mi = 0; mi < 4; mi++) {
                mma16816(acc[mi][n0], ah[mi], bh0, bh1);
                mma16816(acc[mi][n0], ah[mi], bl0, bl1);
                mma16816(acc[mi][n0], al[mi], bh0, bh1);
                mma16816(acc[mi][n1], ah[mi], bh2, bh3);
                mma16816(acc[mi][n1], ah[mi], bl2, bl3);
                mma16816(acc[mi][n1], al[mi], bh2, bh3);
            }
        }
    }

#pragma unroll
    for (int mi = 0; mi < 4; mi++) {
        const int r = bm + wm * 64 + mi * 16 + gid;
#pragma unroll
        for (int ng = 0; ng < 8; ng++) {
            const int col = bn + wn * 64 + ng * 8 + tig * 2;
            *(float2*)&C[(size_t)r * N + col] =
                make_float2(acc[mi][ng][0], acc[mi][ng][1]);
            *(float2*)&C[(size_t)(r + 8) * N + col] =
                make_float2(acc[mi][ng][2], acc[mi][ng][3]);
        }
    }
}

__global__ void __launch_bounds__(256, 1) k_gemm_qkv()
{
    gemm_pre(g_xh, g_xl, g_wqh, g_wql, g_qkv, 3 * DM_);
}

// out projection reads bf16 hi/lo written directly by the attention epilogue
__global__ void __launch_bounds__(256, 1) k_gemm_out(float* __restrict__ out)
{
    gemm_pre(g_aoh, g_aol, g_woh, g_wol, out, DM_);
}

// ---------------- RoPE table (one-time; exact powf/sincosf) ----------------
__global__ void __launch_bounds__(256) k_ropetab(const int* __restrict__ tp)
{
    int idx = blockIdx.x * 256 + threadIdx.x;   // < 65536
    int s = idx >> 5, i = idx & 31;
    float pos = (float)tp[s];
    float inv = powf(10000.0f, -(float)i * (1.0f / 32.0f));
    float sn, cs;
    sincosf(pos * inv, &sn, &cs);
    g_rope_tab[idx] = make_float2(cs, sn);
}

// ---------------- RoPE + bf16 hi/lo split + head layout + V transpose ------
__global__ void __launch_bounds__(256) k_rope()
{
    int idx = blockIdx.x * 256 + threadIdx.x;
    int i = idx & 31;
    int s = (idx >> 5) & (S_ - 1);
    int h = (idx >> 16) & (H_ - 1);
    int b = idx >> 20;

    const int m = b * S_ + s;
    const float* base = g_qkv + (size_t)m * (3 * DM_) + h * DH_;

    float2 cs2 = g_rope_tab[idx & (S_ * 32 - 1)];
    const float cs = cs2.x, sn = cs2.y;

    float qe = base[2 * i],            qo = base[2 * i + 1];
    float ke = base[DM_ + 2 * i],      ko = base[DM_ + 2 * i + 1];
    float ve = base[2 * DM_ + 2 * i],  vo = base[2 * DM_ + 2 * i + 1];

    float rqe = (qe * cs - qo * sn) * 0.125f;
    float rqo = (qo * cs + qe * sn) * 0.125f;
    float rke = ke * cs - ko * sn;
    float rko = ko * cs + ke * sn;

    size_t o = ((size_t)(b * H_ + h) * S_ + s) * DH_ + 2 * i;

    __nv_bfloat16 qh0 = __float2bfloat16(rqe), qh1 = __float2bfloat16(rqo);
    __nv_bfloat16 kh0 = __float2bfloat16(rke), kh1 = __float2bfloat16(rko);
    *(__nv_bfloat162*)&g_qhi[o] = __nv_bfloat162(qh0, qh1);
    *(__nv_bfloat162*)&g_qlo[o] = __nv_bfloat162(
        __float2bfloat16(rqe - __bfloat162float(qh0)),
        __float2bfloat16(rqo - __bfloat162float(qh1)));
    *(__nv_bfloat162*)&g_khi[o] = __nv_bfloat162(kh0, kh1);
    *(__nv_bfloat162*)&g_klo[o] = __nv_bfloat162(
        __float2bfloat16(rke - __bfloat162float(kh0)),
        __float2bfloat16(rko - __bfloat162float(kh1)));

    // V transpose via smem: block = one (b,h), 8 consecutive s
    __shared__ __nv_bfloat16 svh[64][10], svl[64][10];
    const int sl = (threadIdx.x >> 5) & 7;
    __nv_bfloat16 vh0 = __float2bfloat16(ve), vh1 = __float2bfloat16(vo);
    svh[2 * i][sl]     = vh0;
    svh[2 * i + 1][sl] = vh1;
    svl[2 * i][sl]     = __float2bfloat16(ve - __bfloat162float(vh0));
    svl[2 * i + 1][sl] = __float2bfloat16(vo - __bfloat162float(vh1));
    __syncthreads();

    if (threadIdx.x < 128) {
        const int s0  = (blockIdx.x * 8) & (S_ - 1);
        const int idx0 = blockIdx.x * 256;
        const int h0  = (idx0 >> 16) & (H_ - 1);
        const int b0  = idx0 >> 20;
        const int bh  = b0 * H_ + h0;
        const int d   = threadIdx.x >> 1;
        const int sg  = (threadIdx.x & 1) * 4;

        unsigned short uh[4], ul[4];
#pragma unroll
        for (int j = 0; j < 4; j++) {
            uh[j] = *(unsigned short*)&svh[d][sg + j];
            ul[j] = *(unsigned short*)&svl[d][sg + j];
        }
        size_t vo_ = ((size_t)bh * DH_ + d) * S_ + s0 + sg;
        *(uint2*)&g_vthi[vo_] = *(uint2*)uh;
        *(uint2*)&g_vtlo[vo_] = *(uint2*)ul;
    }
}

// ---------------- HMMA flash attention (Q-tile 128, 8 warps) ---------------
// grid (S/128, B*H), 256 threads = 8 warps; warp = 16 q-rows, key tiles of 64.
#define LDK 72     // 144 B stride: 8 distinct 16B phases -> conflict-free ldmatrix

__global__ void __launch_bounds__(256) k_attn_mma()
{
    const int bh  = blockIdx.y;
    const int q0  = blockIdx.x * 128;
    const int tid = threadIdx.x;
    const int lane = tid & 31;
    const int w    = tid >> 5;           // 0..7
    const int gid  = lane >> 2;
    const int tig  = lane & 3;

    const int lr   = lane & 7;
    const int qd   = lane >> 3;
    const int arow = (qd & 1) * 8 + lr;
    const int acol = (qd >> 1) * 8;
    const int brow = (qd >> 1) * 8 + lr;
    const int bcol = (qd & 1) * 8;

    __shared__ __align__(16) __nv_bfloat16 Khi[64][LDK], Klo[64][LDK];
    __shared__ __align__(16) __nv_bfloat16 Vth[64][LDK], Vtl[64][LDK];

    const uint32_t kh_b = smem_u32(&Khi[0][0]);
    const uint32_t kl_b = smem_u32(&Klo[0][0]);
    const uint32_t vh_b = smem_u32(&Vth[0][0]);
    const uint32_t vl_b = smem_u32(&Vtl[0][0]);

    const __nv_bfloat16* qhi = g_qhi + (size_t)bh * S_ * DH_;
    const __nv_bfloat16* qlo = g_qlo + (size_t)bh * S_ * DH_;
    const __nv_bfloat16* khi = g_khi + (size_t)bh * S_ * DH_;
    const __nv_bfloat16* klo = g_klo + (size_t)bh * S_ * DH_;
    const __nv_bfloat16* vth = g_vthi + (size_t)bh * DH_ * S_;
    const __nv_bfloat16* vtl = g_vtlo + (size_t)bh * DH_ * S_;

    // ---- stage 128-row Q tile: rows 0..63 in Khi/Klo, 64..127 in Vth/Vtl ---
    {
        const int rowQ = tid >> 1;            // 0..127
        const int sgQ  = (tid & 1) * 4;
#pragma unroll
        for (int i2 = 0; i2 < 4; i2++) {
            const int sg = (sgQ + i2) * 8;
            uint4 vh = *(const uint4*)(qhi + (size_t)(q0 + rowQ) * DH_ + sg);
            uint4 vl = *(const uint4*)(qlo + (size_t)(q0 + rowQ) * DH_ + sg);
            if (rowQ < 64) {
                *(uint4*)&Khi[rowQ][sg] = vh;
                *(uint4*)&Klo[rowQ][sg] = vl;
            } else {
                *(uint4*)&Vth[rowQ - 64][sg] = vh;
                *(uint4*)&Vtl[rowQ - 64][sg] = vl;
            }
        }
    }
    __syncthreads();

    uint32_t qh[4][4], ql[4][4];
    {
        const uint32_t qb_h = (w < 4) ? kh_b : vh_b;
        const uint32_t qb_l = (w < 4) ? kl_b : vl_b;
        const int qr = (w & 3) * 16;
#pragma unroll
        for (int kb = 0; kb < 4; kb++) {
            const uint32_t off =
                (uint32_t)((qr + arow) * LDK + kb * 16 + acol) * 2;
            ldsm4(qh[kb][0], qh[kb][1], qh[kb][2], qh[kb][3], qb_h + off);
            ldsm4(ql[kb][0], ql[kb][1], ql[kb][2], ql[kb][3], qb_l + off);
        }
    }
    __syncthreads();

    float o[8][4];
#pragma unroll
    for (int j = 0; j < 8; j++)
#pragma unroll
        for (int c = 0; c < 4; c++) o[j][c] = 0.0f;
    float m0 = -INFINITY, m1 = -INFINITY, l0 = 0.0f, l1 = 0.0f;

    const int r0a = q0 + w * 16 + gid;
    const int rmax = q0 + w * 16 + 15;       // last q-row this warp owns

    const int rowK = tid >> 2;               // 0..63
    const int sgK0 = (tid & 3) * 2;

    for (int kt = 0; kt <= q0 + 64; kt += 64) {
#pragma unroll
        for (int i2 = 0; i2 < 2; i2++) {
            const int sg = (sgK0 + i2) * 8;
            *(uint4*)&Khi[rowK][sg] =
                *(const uint4*)(khi + (size_t)(kt + rowK) * DH_ + sg);
            *(uint4*)&Klo[rowK][sg] =
                *(const uint4*)(klo + (size_t)(kt + rowK) * DH_ + sg);
            *(uint4*)&Vth[rowK][sg] =
                *(const uint4*)(vth + (size_t)rowK * S_ + kt + sg);
            *(uint4*)&Vtl[rowK][sg] =
                *(const uint4*)(vtl + (size_t)rowK * S_ + kt + sg);
        }
        __syncthreads();

        if (kt <= rmax) {                    // warp has unmasked keys here
            float s[8][4];
#pragma unroll
            for (int j = 0; j < 8; j++)
#pragma unroll
                for (int c = 0; c < 4; c++) s[j][c] = 0.0f;

#pragma unroll
            for (int kb = 0; kb < 4; kb++) {
#pragma unroll
                for (int jp = 0; jp < 4; jp++) {
                    const uint32_t off =
                        (uint32_t)((jp * 16 + brow) * LDK + kb * 16 + bcol) * 2;
                    uint32_t kh0, kh1, kh2, kh3, kl0, kl1, kl2, kl3;
                    ldsm4(kh0, kh1, kh2, kh3, kh_b + off);
                    ldsm4(kl0, kl1, kl2, kl3, kl_b + off);
                    const int j0 = jp * 2, j1 = jp * 2 + 1;
                    mma16816(s[j0], qh[kb], kh0, kh1);
                    mma16816(s[j0], qh[kb], kl0, kl1);
                    mma16816(s[j0], ql[kb], kh0, kh1);
                    mma16816(s[j1], qh[kb], kh2, kh3);
                    mma16816(s[j1], qh[kb], kl2, kl3);
                    mma16816(s[j1], ql[kb], kh2, kh3);
                }
            }

            if (kt + 63 > rmax - 15) {       // tile may cross this warp's diagonal
#pragma unroll
                for (int j = 0; j < 8; j++) {
                    const int cb = kt + j * 8 + 2 * tig;
                    if (cb     > r0a)     s[j][0] = -INFINITY;
                    if (cb + 1 > r0a)     s[j][1] = -INFINITY;
                    if (cb     > r0a + 8) s[j][2] = -INFINITY;
                    if (cb + 1 > r0a + 8) s[j][3] = -INFINITY;
                }
            }

            float tm0 = m0, tm1 = m1;
#pragma unroll
            for (int j = 0; j < 8; j++) {
                tm0 = fmaxf(tm0, fmaxf(s[j][0], s[j][1]));
                tm1 = fmaxf(tm1, fmaxf(s[j][2], s[j][3]));
            }
            tm0 = fmaxf(tm0, __shfl_xor_sync(0xffffffff, tm0, 1));
            tm0 = fmaxf(tm0, __shfl_xor_sync(0xffffffff, tm0, 2));
            tm1 = fmaxf(tm1, __shfl_xor_sync(0xffffffff, tm1, 1));
            tm1 = fmaxf(tm1, __shfl_xor_sync(0xffffffff, tm1, 2));

            const float sc0 = __expf(m0 - tm0);
            const float sc1 = __expf(m1 - tm1);
            m0 = tm0; m1 = tm1;
            l0 *= sc0; l1 *= sc1;
#pragma unroll
            for (int j = 0; j < 8; j++) {
                o[j][0] *= sc0; o[j][1] *= sc0;
                o[j][2] *= sc1; o[j][3] *= sc1;
            }

            float rs0 = 0.0f, rs1 = 0.0f;
#pragma unroll
            for (int j = 0; j < 8; j++) {
                s[j][0] = __expf(s[j][0] - m0);
                s[j][1] = __expf(s[j][1] - m0);
                s[j][2] = __expf(s[j][2] - m1);
                s[j][3] = __expf(s[j][3] - m1);
                rs0 += s[j][0] + s[j][1];
                rs1 += s[j][2] + s[j][3];
            }
            rs0 += __shfl_xor_sync(0xffffffff, rs0, 1);
            rs0 += __shfl_xor_sync(0xffffffff, rs0, 2);
            rs1 += __shfl_xor_sync(0xffffffff, rs1, 1);
            rs1 += __shfl_xor_sync(0xffffffff, rs1, 2);
            l0 += rs0; l1 += rs1;

            uint32_t ph[4][4], pl[4][4];
#pragma unroll
            for (int kb = 0; kb < 4; kb++) {
                const int j0 = 2 * kb, j1 = 2 * kb + 1;
                ph[kb][0] = pack_bf16(s[j0][0], s[j0][1]);
                ph[kb][1] = pack_bf16(s[j0][2], s[j0][3]);
                ph[kb][2] = pack_bf16(s[j1][0], s[j1][1]);
                ph[kb][3] = pack_bf16(s[j1][2], s[j1][3]);
                __nv_bfloat162 h0 = *(__nv_bfloat162*)&ph[kb][0];
                __nv_bfloat162 h1 = *(__nv_bfloat162*)&ph[kb][1];
                __nv_bfloat162 h2 = *(__nv_bfloat162*)&ph[kb][2];
                __nv_bfloat162 h3 = *(__nv_bfloat162*)&ph[kb][3];
                pl[kb][0] = pack_bf16(s[j0][0] - __bfloat162float(h0.x),
                                      s[j0][1] - __bfloat162float(h0.y));
                pl[kb][1] = pack_bf16(s[j0][2] - __bfloat162float(h1.x),
                                      s[j0][3] - __bfloat162float(h1.y));
                pl[kb][2] = pack_bf16(s[j1][0] - __bfloat162float(h2.x),
                                      s[j1][1] - __bfloat162float(h2.y));
                pl[kb][3] = pack_bf16(s[j1][2] - __bfloat162float(h3.x),
                                      s[j1][3] - __bfloat162float(h3.y));
            }

#pragma unroll
            for (int kb = 0; kb < 4; kb++) {
#pragma unroll
                for (int jp = 0; jp < 4; jp++) {
                    const uint32_t off =
                        (uint32_t)((jp * 16 + brow) * LDK + kb * 16 + bcol) * 2;
                    uint32_t vh0, vh1, vh2, vh3, vl0, vl1, vl2, vl3;
                    ldsm4(vh0, vh1, vh2, vh3, vh_b + off);
                    ldsm4(vl0, vl1, vl2, vl3, vl_b + off);
                    const int j0 = jp * 2, j1 = jp * 2 + 1;
                    mma16816(o[j0], ph[kb], vh0, vh1);
                    mma16816(o[j0], ph[kb], vl0, vl1);
                    mma16816(o[j0], pl[kb], vh0, vh1);
                    mma16816(o[j1], ph[kb], vh2, vh3);
                    mma16816(o[j1], ph[kb], vl2, vl3);
                    mma16816(o[j1], pl[kb], vh2, vh3);
                }
            }
        }
        __syncthreads();
    }

    // ---- epilogue: normalize + direct bf16 hi/lo split into g_aoh/g_aol ----
    const float inv0 = 1.0f / l0;
    const float inv1 = 1.0f / l1;
    const int b = bh >> 4, h = bh & 15;
#pragma unroll
    for (int j = 0; j < 8; j++) {
        const int col = h * DH_ + j * 8 + 2 * tig;
        const size_t i0 = (size_t)(b * S_ + r0a) * DM_ + col;
        const size_t i1 = (size_t)(b * S_ + r0a + 8) * DM_ + col;

        float x0 = o[j][0] * inv0, y0 = o[j][1] * inv0;
        float x1 = o[j][2] * inv1, y1 = o[j][3] * inv1;

        uint32_t h0 = pack_bf16(x0, y0);
        uint32_t h1 = pack_bf16(x1, y1);
        __nv_bfloat162 hh0 = *(__nv_bfloat162*)&h0;
        __nv_bfloat162 hh1 = *(__nv_bfloat162*)&h1;
        uint32_t l0p = pack_bf16(x0 - __bfloat162float(hh0.x),
                                 y0 - __bfloat162float(hh0.y));
        uint32_t l1p = pack_bf16(x1 - __bfloat162float(hh1.x),
                                 y1 - __bfloat162float(hh1.y));

        *(uint32_t*)&g_aoh[i0] = h0;
        *(uint32_t*)&g_aol[i0] = l0p;
        *(uint32_t*)&g_aoh[i1] = h1;
        *(uint32_t*)&g_aol[i1] = l1p;
    }
}

// ---------------- launch ----------------
extern "C" void kernel_launch(void* const* d_in, const int* in_sizes, int n_in,
                              void* d_out, int out_size)
{
    const float* x      = (const float*)d_in[0];
    const float* w_qkv  = (const float*)d_in[1];
    const float* w_o    = (const float*)d_in[2];
    const int*   tp     = (const int*)d_in[3];

    static bool attr_done = false;
    if (!attr_done) {
        cudaFuncSetAttribute(k_gemm_qkv,
            cudaFuncAttributeMaxDynamicSharedMemorySize, GEMM_SMEM_B);
        cudaFuncSetAttribute(k_gemm_out,
            cudaFuncAttributeMaxDynamicSharedMemorySize, GEMM_SMEM_B);
        attr_done = true;
    }

    // 0) one-time bf16 hi/lo splits + rope table
    k_splitg<<<(MTOK * DM_) / 1024, 256>>>(x, 0);
    k_splitg<<<(3 * DM_ * DM_) / 1024, 256>>>(w_qkv, 1);
    k_splitg<<<(DM_ * DM_) / 1024, 256>>>(w_o, 2);
    k_ropetab<<<(S_ * 32) / 256, 256>>>(tp);

    // 1) QKV projection
    k_gemm_qkv<<<dim3(3 * DM_ / 256, MTOK / 128), 256, GEMM_SMEM_B>>>();

    // 2) RoPE + bf16 hi/lo per-head layout + V transpose
    k_rope<<<(B_ * H_ * S_ * 32) / 256, 256>>>();

    // 3) causal flash attention (Q-tile 128, fused output split)
    k_attn_mma<<<dim3(S_ / 128, B_ * H_), 256>>>();

    // 4) output projection (reads g_aoh/g_aol written by attention)
    k_gemm_out<<<dim3(DM_ / 256, MTOK / 128), 256, GEMM_SMEM_B>>>((float*)d_out);
}

// round 14
// speedup vs baseline: 1.4922x; 1.4922x over previous
#include <cuda_runtime.h>
#include <cuda_bf16.h>
#include <cstdint>
#include <math.h>

#define B_   2
#define S_   2048
#define H_   16
#define DH_  64
#define DM_  1024
#define MTOK (B_ * S_)        // 4096

// ---------------- scratch (device-code references ONLY) ----------------
__device__ float g_qkv[(size_t)MTOK * 3 * DM_];     // 48 MB
__device__ float2 g_rope_tab[S_ * 32];              // cos/sin per (s, i)

// bf16 hi/lo GEMM operands
__device__ __nv_bfloat16 g_xh [(size_t)MTOK * DM_];
__device__ __nv_bfloat16 g_xl [(size_t)MTOK * DM_];
__device__ __nv_bfloat16 g_wqh[(size_t)3 * DM_ * DM_];
__device__ __nv_bfloat16 g_wql[(size_t)3 * DM_ * DM_];
__device__ __nv_bfloat16 g_woh[(size_t)DM_ * DM_];
__device__ __nv_bfloat16 g_wol[(size_t)DM_ * DM_];
__device__ __nv_bfloat16 g_aoh[(size_t)MTOK * DM_];
__device__ __nv_bfloat16 g_aol[(size_t)MTOK * DM_];

// bf16 hi/lo attention operands (Q has 0.125 score scale folded in)
__device__ __nv_bfloat16 g_qhi[(size_t)B_ * H_ * S_ * DH_];
__device__ __nv_bfloat16 g_qlo[(size_t)B_ * H_ * S_ * DH_];
__device__ __nv_bfloat16 g_khi[(size_t)B_ * H_ * S_ * DH_];
__device__ __nv_bfloat16 g_klo[(size_t)B_ * H_ * S_ * DH_];
__device__ __nv_bfloat16 g_vthi[(size_t)B_ * H_ * DH_ * S_];  // transposed [bh][d][s]
__device__ __nv_bfloat16 g_vtlo[(size_t)B_ * H_ * DH_ * S_];

// ---------------- helpers ----------------
__device__ __forceinline__ uint32_t smem_u32(const void* p) {
    uint32_t a;
    asm("{ .reg .u64 t; cvta.to.shared.u64 t, %1; cvt.u32.u64 %0, t; }"
        : "=r"(a) : "l"(p));
    return a;
}

__device__ __forceinline__ void mma16816(float* d, const uint32_t* a,
                                         uint32_t b0, uint32_t b1) {
    asm volatile(
        "mma.sync.aligned.m16n8k16.row.col.f32.bf16.bf16.f32 "
        "{%0,%1,%2,%3}, {%4,%5,%6,%7}, {%8,%9}, {%0,%1,%2,%3};"
        : "+f"(d[0]), "+f"(d[1]), "+f"(d[2]), "+f"(d[3])
        : "r"(a[0]), "r"(a[1]), "r"(a[2]), "r"(a[3]), "r"(b0), "r"(b1));
}

__device__ __forceinline__ void ldsm4(uint32_t& r0, uint32_t& r1,
                                      uint32_t& r2, uint32_t& r3, uint32_t addr) {
    asm volatile("ldmatrix.sync.aligned.m8n8.x4.shared.b16 {%0,%1,%2,%3}, [%4];"
                 : "=r"(r0), "=r"(r1), "=r"(r2), "=r"(r3) : "r"(addr));
}

__device__ __forceinline__ uint32_t pack_bf16(float x, float y) {
    __nv_bfloat162 t(__float2bfloat16(x), __float2bfloat16(y));
    return *(uint32_t*)&t;
}

// ---------------- fp32 -> bf16 hi/lo split (one-time, streaming) ----------
__global__ void __launch_bounds__(256) k_splitg(const float* __restrict__ in,
                                                int which)
{
    __nv_bfloat16 *hi, *lo;
    if      (which == 0) { hi = g_xh;  lo = g_xl;  }
    else if (which == 1) { hi = g_wqh; lo = g_wql; }
    else                 { hi = g_woh; lo = g_wol; }

    int i = (blockIdx.x * 256 + threadIdx.x) * 4;
    float4 v = *(const float4*)(in + i);
    __nv_bfloat16 h0 = __float2bfloat16(v.x);
    __nv_bfloat16 h1 = __float2bfloat16(v.y);
    __nv_bfloat16 h2 = __float2bfloat16(v.z);
    __nv_bfloat16 h3 = __float2bfloat16(v.w);
    *(__nv_bfloat162*)(hi + i)     = __nv_bfloat162(h0, h1);
    *(__nv_bfloat162*)(hi + i + 2) = __nv_bfloat162(h2, h3);
    *(__nv_bfloat162*)(lo + i)     = __nv_bfloat162(
        __float2bfloat16(v.x - __bfloat162float(h0)),
        __float2bfloat16(v.y - __bfloat162float(h1)));
    *(__nv_bfloat162*)(lo + i + 2) = __nv_bfloat162(
        __float2bfloat16(v.z - __bfloat162float(h2)),
        __float2bfloat16(v.w - __bfloat162float(h3)));
}

// ---------------- HMMA split-bf16 GEMM (R12-proven) ------------------------
// CTA tile 128x256, BK=16, double-buffered smem, 8 warps (2x4), warp 64x64.
#define LDT 24                         // halves per smem row (48 B stride)
#define A_TILE_H (128 * LDT)           // 3072 halves
#define B_TILE_H (256 * LDT)           // 6144 halves
#define BUF_H    (2 * A_TILE_H + 2 * B_TILE_H)   // 18432 halves
#define GEMM_SMEM_B (2 * BUF_H * 2)    // 73728 bytes

__device__ __forceinline__ void gemm_pre(const __nv_bfloat16* __restrict__ Ahi,
                                         const __nv_bfloat16* __restrict__ Alo,
                                         const __nv_bfloat16* __restrict__ Bhi,
                                         const __nv_bfloat16* __restrict__ Blo,
                                         float* __restrict__ C, int N)
{
    extern __shared__ __align__(16) __nv_bfloat16 sm[];
    const uint32_t sm0 = smem_u32(sm);

    const int tid  = threadIdx.x;
    const int lane = tid & 31;
    const int wid  = tid >> 5;
    const int wm   = wid & 1;
    const int wn   = wid >> 1;
    const int gid  = lane >> 2;
    const int tig  = lane & 3;
    const int bm   = blockIdx.y * 128;
    const int bn   = blockIdx.x * 256;

    const int lr   = lane & 7;
    const int qd   = lane >> 3;
    const int arow = (qd & 1) * 8 + lr;
    const int acol = (qd >> 1) * 8;
    const int brow = (qd >> 1) * 8 + lr;
    const int bcol = (qd & 1) * 8;

    const int rowA = tid >> 1;
    const int sgA  = tid & 1;

    float acc[4][8][4];
#pragma unroll
    for (int i = 0; i < 4; i++)
#pragma unroll
        for (int j = 0; j < 8; j++)
#pragma unroll
            for (int k = 0; k < 4; k++) acc[i][j][k] = 0.0f;

    uint4 pah, pal, pbh[2], pbl[2];

    auto fetch = [&](int c) {
        const int kk = c << 4;
        const int ke = kk + sgA * 8;
        pah = *(const uint4*)(Ahi + (size_t)(bm + rowA) * DM_ + ke);
        pal = *(const uint4*)(Alo + (size_t)(bm + rowA) * DM_ + ke);
#pragma unroll
        for (int i = 0; i < 2; i++) {
            const int idx = i * 256 + tid;
            const int rb  = idx >> 1;
            const int keb = kk + (idx & 1) * 8;
            pbh[i] = *(const uint4*)(Bhi + (size_t)(bn + rb) * DM_ + keb);
            pbl[i] = *(const uint4*)(Blo + (size_t)(bn + rb) * DM_ + keb);
        }
    };

    fetch(0);

    const int NC = DM_ / 16;
    for (int c = 0; c < NC; c++) {
        const int buf = c & 1;
        __nv_bfloat16* base = sm + buf * BUF_H;

        *(uint4*)&base[rowA * LDT + sgA * 8] = pah;
        *(uint4*)&base[A_TILE_H + rowA * LDT + sgA * 8] = pal;
#pragma unroll
        for (int i = 0; i < 2; i++) {
            const int idx = i * 256 + tid;
            const int rb  = idx >> 1;
            const int sg  = (idx & 1) * 8;
            *(uint4*)&base[2 * A_TILE_H + rb * LDT + sg] = pbh[i];
            *(uint4*)&base[2 * A_TILE_H + B_TILE_H + rb * LDT + sg] = pbl[i];
        }
        __syncthreads();

        if (c + 1 < NC) fetch(c + 1);

        const uint32_t bufb = sm0 + (uint32_t)buf * BUF_H * 2;

        uint32_t ah[4][4], al[4][4];
#pragma unroll
        for (int mi = 0; mi < 4; mi++) {
            const uint32_t aoff =
                (uint32_t)((wm * 64 + mi * 16 + arow) * LDT + acol) * 2;
            ldsm4(ah[mi][0], ah[mi][1], ah[mi][2], ah[mi][3], bufb + aoff);
            ldsm4(al[mi][0], al[mi][1], al[mi][2], al[mi][3],
                  bufb + A_TILE_H * 2 + aoff);
        }
#pragma unroll
        for (int pg = 0; pg < 4; pg++) {
            const uint32_t boff =
                (uint32_t)((wn * 64 + pg * 16 + brow) * LDT + bcol) * 2;
            uint32_t bh0, bh1, bh2, bh3, bl0, bl1, bl2, bl3;
            ldsm4(bh0, bh1, bh2, bh3, bufb + 4 * A_TILE_H + boff);
            ldsm4(bl0, bl1, bl2, bl3, bufb + 4 * A_TILE_H + B_TILE_H * 2 + boff);
            const int n0 = pg * 2, n1 = pg * 2 + 1;
#pragma unroll
            for (int mi = 0; mi < 4; mi++) {
                mma16816(acc[mi][n0], ah[mi], bh0, bh1);
                mma16816(acc[mi][n0], ah[mi], bl0, bl1);
                mma16816(acc[mi][n0], al[mi], bh0, bh1);
                mma16816(acc[mi][n1], ah[mi], bh2, bh3);
                mma16816(acc[mi][n1], ah[mi], bl2, bl3);
                mma16816(acc[mi][n1], al[mi], bh2, bh3);
            }
        }
    }

#pragma unroll
    for (int mi = 0; mi < 4; mi++) {
        const int r = bm + wm * 64 + mi * 16 + gid;
#pragma unroll
        for (int ng = 0; ng < 8; ng++) {
            const int col = bn + wn * 64 + ng * 8 + tig * 2;
            *(float2*)&C[(size_t)r * N + col] =
                make_float2(acc[mi][ng][0], acc[mi][ng][1]);
            *(float2*)&C[(size_t)(r + 8) * N + col] =
                make_float2(acc[mi][ng][2], acc[mi][ng][3]);
        }
    }
}

__global__ void __launch_bounds__(256, 1) k_gemm_qkv()
{
    gemm_pre(g_xh, g_xl, g_wqh, g_wql, g_qkv, 3 * DM_);
}

// out projection reads bf16 hi/lo written directly by the attention epilogue
__global__ void __launch_bounds__(256, 1) k_gemm_out(float* __restrict__ out)
{
    gemm_pre(g_aoh, g_aol, g_woh, g_wol, out, DM_);
}

// ---------------- RoPE table (one-time; exact powf/sincosf) ----------------
__global__ void __launch_bounds__(256) k_ropetab(const int* __restrict__ tp)
{
    int idx = blockIdx.x * 256 + threadIdx.x;   // < 65536
    int s = idx >> 5, i = idx & 31;
    float pos = (float)tp[s];
    float inv = powf(10000.0f, -(float)i * (1.0f / 32.0f));
    float sn, cs;
    sincosf(pos * inv, &sn, &cs);
    g_rope_tab[idx] = make_float2(cs, sn);
}

// ---------------- RoPE + bf16 hi/lo split + head layout + V transpose ------
__global__ void __launch_bounds__(256) k_rope()
{
    int idx = blockIdx.x * 256 + threadIdx.x;
    int i = idx & 31;
    int s = (idx >> 5) & (S_ - 1);
    int h = (idx >> 16) & (H_ - 1);
    int b = idx >> 20;

    const int m = b * S_ + s;
    const float* base = g_qkv + (size_t)m * (3 * DM_) + h * DH_;

    float2 cs2 = g_rope_tab[idx & (S_ * 32 - 1)];
    const float cs = cs2.x, sn = cs2.y;

    float qe = base[2 * i],            qo = base[2 * i + 1];
    float ke = base[DM_ + 2 * i],      ko = base[DM_ + 2 * i + 1];
    float ve = base[2 * DM_ + 2 * i],  vo = base[2 * DM_ + 2 * i + 1];

    float rqe = (qe * cs - qo * sn) * 0.125f;
    float rqo = (qo * cs + qe * sn) * 0.125f;
    float rke = ke * cs - ko * sn;
    float rko = ko * cs + ke * sn;

    size_t o = ((size_t)(b * H_ + h) * S_ + s) * DH_ + 2 * i;

    __nv_bfloat16 qh0 = __float2bfloat16(rqe), qh1 = __float2bfloat16(rqo);
    __nv_bfloat16 kh0 = __float2bfloat16(rke), kh1 = __float2bfloat16(rko);
    *(__nv_bfloat162*)&g_qhi[o] = __nv_bfloat162(qh0, qh1);
    *(__nv_bfloat162*)&g_qlo[o] = __nv_bfloat162(
        __float2bfloat16(rqe - __bfloat162float(qh0)),
        __float2bfloat16(rqo - __bfloat162float(qh1)));
    *(__nv_bfloat162*)&g_khi[o] = __nv_bfloat162(kh0, kh1);
    *(__nv_bfloat162*)&g_klo[o] = __nv_bfloat162(
        __float2bfloat16(rke - __bfloat162float(kh0)),
        __float2bfloat16(rko - __bfloat162float(kh1)));

    // V transpose via smem: block = one (b,h), 8 consecutive s
    __shared__ __nv_bfloat16 svh[64][10], svl[64][10];
    const int sl = (threadIdx.x >> 5) & 7;
    __nv_bfloat16 vh0 = __float2bfloat16(ve), vh1 = __float2bfloat16(vo);
    svh[2 * i][sl]     = vh0;
    svh[2 * i + 1][sl] = vh1;
    svl[2 * i][sl]     = __float2bfloat16(ve - __bfloat162float(vh0));
    svl[2 * i + 1][sl] = __float2bfloat16(vo - __bfloat162float(vh1));
    __syncthreads();

    if (threadIdx.x < 128) {
        const int s0  = (blockIdx.x * 8) & (S_ - 1);
        const int idx0 = blockIdx.x * 256;
        const int h0  = (idx0 >> 16) & (H_ - 1);
        const int b0  = idx0 >> 20;
        const int bh  = b0 * H_ + h0;
        const int d   = threadIdx.x >> 1;
        const int sg  = (threadIdx.x & 1) * 4;

        unsigned short uh[4], ul[4];
#pragma unroll
        for (int j = 0; j < 4; j++) {
            uh[j] = *(unsigned short*)&svh[d][sg + j];
            ul[j] = *(unsigned short*)&svl[d][sg + j];
        }
        size_t vo_ = ((size_t)bh * DH_ + d) * S_ + s0 + sg;
        *(uint2*)&g_vthi[vo_] = *(uint2*)uh;
        *(uint2*)&g_vtlo[vo_] = *(uint2*)ul;
    }
}

// ---------------- HMMA flash attention (R12-proven core, fused epilogue) ---
// grid (S/64, B*H), 128 threads = 4 warps; warp = 16 q-rows, key tiles of 64.
#define LDK 72     // 144 B stride: 8 distinct 16B phases -> conflict-free ldmatrix

__global__ void __launch_bounds__(128) k_attn_mma()
{
    const int bh  = blockIdx.y;
    const int q0  = blockIdx.x * 64;
    const int tid = threadIdx.x;
    const int lane = tid & 31;
    const int w    = tid >> 5;
    const int gid  = lane >> 2;
    const int tig  = lane & 3;

    const int lr   = lane & 7;
    const int qd   = lane >> 3;
    const int arow = (qd & 1) * 8 + lr;
    const int acol = (qd >> 1) * 8;
    const int brow = (qd >> 1) * 8 + lr;
    const int bcol = (qd & 1) * 8;

    __shared__ __align__(16) __nv_bfloat16 Khi[64][LDK], Klo[64][LDK];
    __shared__ __align__(16) __nv_bfloat16 Vth[64][LDK], Vtl[64][LDK];

    const uint32_t kh_b = smem_u32(&Khi[0][0]);
    const uint32_t kl_b = smem_u32(&Klo[0][0]);
    const uint32_t vh_b = smem_u32(&Vth[0][0]);
    const uint32_t vl_b = smem_u32(&Vtl[0][0]);

    const __nv_bfloat16* qhi = g_qhi + (size_t)bh * S_ * DH_;
    const __nv_bfloat16* qlo = g_qlo + (size_t)bh * S_ * DH_;
    const __nv_bfloat16* khi = g_khi + (size_t)bh * S_ * DH_;
    const __nv_bfloat16* klo = g_klo + (size_t)bh * S_ * DH_;
    const __nv_bfloat16* vth = g_vthi + (size_t)bh * DH_ * S_;
    const __nv_bfloat16* vtl = g_vtlo + (size_t)bh * DH_ * S_;

    const int row0 = tid >> 1;            // 0..63
    const int seg0 = (tid & 1) * 4;       // 16B segs {0..3} or {4..7}

    // ---- stage Q tile (reuse K smem), extract fragments via ldmatrix ----
#pragma unroll
    for (int i2 = 0; i2 < 4; i2++) {
        *(uint4*)&Khi[row0][(seg0 + i2) * 8] =
            *(const uint4*)(qhi + (size_t)(q0 + row0) * DH_ + (seg0 + i2) * 8);
        *(uint4*)&Klo[row0][(seg0 + i2) * 8] =
            *(const uint4*)(qlo + (size_t)(q0 + row0) * DH_ + (seg0 + i2) * 8);
    }
    __syncthreads();

    uint32_t qh[4][4], ql[4][4];
#pragma unroll
    for (int kb = 0; kb < 4; kb++) {
        const uint32_t off =
            (uint32_t)((w * 16 + arow) * LDK + kb * 16 + acol) * 2;
        ldsm4(qh[kb][0], qh[kb][1], qh[kb][2], qh[kb][3], kh_b + off);
        ldsm4(ql[kb][0], ql[kb][1], ql[kb][2], ql[kb][3], kl_b + off);
    }
    __syncthreads();

    float o[8][4];
#pragma unroll
    for (int j = 0; j < 8; j++)
#pragma unroll
        for (int c = 0; c < 4; c++) o[j][c] = 0.0f;
    float m0 = -INFINITY, m1 = -INFINITY, l0 = 0.0f, l1 = 0.0f;

    const int r0a = q0 + w * 16 + gid;

    for (int kt = 0; kt <= q0; kt += 64) {
#pragma unroll
        for (int i2 = 0; i2 < 4; i2++) {
            const int sg = (seg0 + i2) * 8;
            *(uint4*)&Khi[row0][sg] =
                *(const uint4*)(khi + (size_t)(kt + row0) * DH_ + sg);
            *(uint4*)&Klo[row0][sg] =
                *(const uint4*)(klo + (size_t)(kt + row0) * DH_ + sg);
            *(uint4*)&Vth[row0][sg] =
                *(const uint4*)(vth + (size_t)row0 * S_ + kt + sg);
            *(uint4*)&Vtl[row0][sg] =
                *(const uint4*)(vtl + (size_t)row0 * S_ + kt + sg);
        }
        __syncthreads();

        float s[8][4];
#pragma unroll
        for (int j = 0; j < 8; j++)
#pragma unroll
            for (int c = 0; c < 4; c++) s[j][c] = 0.0f;

#pragma unroll
        for (int kb = 0; kb < 4; kb++) {
#pragma unroll
            for (int jp = 0; jp < 4; jp++) {
                const uint32_t off =
                    (uint32_t)((jp * 16 + brow) * LDK + kb * 16 + bcol) * 2;
                uint32_t kh0, kh1, kh2, kh3, kl0, kl1, kl2, kl3;
                ldsm4(kh0, kh1, kh2, kh3, kh_b + off);
                ldsm4(kl0, kl1, kl2, kl3, kl_b + off);
                const int j0 = jp * 2, j1 = jp * 2 + 1;
                mma16816(s[j0], qh[kb], kh0, kh1);
                mma16816(s[j0], qh[kb], kl0, kl1);
                mma16816(s[j0], ql[kb], kh0, kh1);
                mma16816(s[j1], qh[kb], kh2, kh3);
                mma16816(s[j1], qh[kb], kl2, kl3);
                mma16816(s[j1], ql[kb], kh2, kh3);
            }
        }

        if (kt == q0) {
#pragma unroll
            for (int j = 0; j < 8; j++) {
                const int cb = kt + j * 8 + 2 * tig;
                if (cb     > r0a)     s[j][0] = -INFINITY;
                if (cb + 1 > r0a)     s[j][1] = -INFINITY;
                if (cb     > r0a + 8) s[j][2] = -INFINITY;
                if (cb + 1 > r0a + 8) s[j][3] = -INFINITY;
            }
        }

        float tm0 = m0, tm1 = m1;
#pragma unroll
        for (int j = 0; j < 8; j++) {
            tm0 = fmaxf(tm0, fmaxf(s[j][0], s[j][1]));
            tm1 = fmaxf(tm1, fmaxf(s[j][2], s[j][3]));
        }
        tm0 = fmaxf(tm0, __shfl_xor_sync(0xffffffff, tm0, 1));
        tm0 = fmaxf(tm0, __shfl_xor_sync(0xffffffff, tm0, 2));
        tm1 = fmaxf(tm1, __shfl_xor_sync(0xffffffff, tm1, 1));
        tm1 = fmaxf(tm1, __shfl_xor_sync(0xffffffff, tm1, 2));

        const float sc0 = __expf(m0 - tm0);
        const float sc1 = __expf(m1 - tm1);
        m0 = tm0; m1 = tm1;
        l0 *= sc0; l1 *= sc1;
#pragma unroll
        for (int j = 0; j < 8; j++) {
            o[j][0] *= sc0; o[j][1] *= sc0;
            o[j][2] *= sc1; o[j][3] *= sc1;
        }

        float rs0 = 0.0f, rs1 = 0.0f;
#pragma unroll
        for (int j = 0; j < 8; j++) {
            s[j][0] = __expf(s[j][0] - m0);
            s[j][1] = __expf(s[j][1] - m0);
            s[j][2] = __expf(s[j][2] - m1);
            s[j][3] = __expf(s[j][3] - m1);
            rs0 += s[j][0] + s[j][1];
            rs1 += s[j][2] + s[j][3];
        }
        rs0 += __shfl_xor_sync(0xffffffff, rs0, 1);
        rs0 += __shfl_xor_sync(0xffffffff, rs0, 2);
        rs1 += __shfl_xor_sync(0xffffffff, rs1, 1);
        rs1 += __shfl_xor_sync(0xffffffff, rs1, 2);
        l0 += rs0; l1 += rs1;

        uint32_t ph[4][4], pl[4][4];
#pragma unroll
        for (int kb = 0; kb < 4; kb++) {
            const int j0 = 2 * kb, j1 = 2 * kb + 1;
            ph[kb][0] = pack_bf16(s[j0][0], s[j0][1]);
            ph[kb][1] = pack_bf16(s[j0][2], s[j0][3]);
            ph[kb][2] = pack_bf16(s[j1][0], s[j1][1]);
            ph[kb][3] = pack_bf16(s[j1][2], s[j1][3]);
            __nv_bfloat162 h0 = *(__nv_bfloat162*)&ph[kb][0];
            __nv_bfloat162 h1 = *(__nv_bfloat162*)&ph[kb][1];
            __nv_bfloat162 h2 = *(__nv_bfloat162*)&ph[kb][2];
            __nv_bfloat162 h3 = *(__nv_bfloat162*)&ph[kb][3];
            pl[kb][0] = pack_bf16(s[j0][0] - __bfloat162float(h0.x),
                                  s[j0][1] - __bfloat162float(h0.y));
            pl[kb][1] = pack_bf16(s[j0][2] - __bfloat162float(h1.x),
                                  s[j0][3] - __bfloat162float(h1.y));
            pl[kb][2] = pack_bf16(s[j1][0] - __bfloat162float(h2.x),
                                  s[j1][1] - __bfloat162float(h2.y));
            pl[kb][3] = pack_bf16(s[j1][2] - __bfloat162float(h3.x),
                                  s[j1][3] - __bfloat162float(h3.y));
        }

#pragma unroll
        for (int kb = 0; kb < 4; kb++) {
#pragma unroll
            for (int jp = 0; jp < 4; jp++) {
                const uint32_t off =
                    (uint32_t)((jp * 16 + brow) * LDK + kb * 16 + bcol) * 2;
                uint32_t vh0, vh1, vh2, vh3, vl0, vl1, vl2, vl3;
                ldsm4(vh0, vh1, vh2, vh3, vh_b + off);
                ldsm4(vl0, vl1, vl2, vl3, vl_b + off);
                const int j0 = jp * 2, j1 = jp * 2 + 1;
                mma16816(o[j0], ph[kb], vh0, vh1);
                mma16816(o[j0], ph[kb], vl0, vl1);
                mma16816(o[j0], pl[kb], vh0, vh1);
                mma16816(o[j1], ph[kb], vh2, vh3);
                mma16816(o[j1], ph[kb], vl2, vl3);
                mma16816(o[j1], pl[kb], vh2, vh3);
            }
        }
        __syncthreads();
    }

    // ---- epilogue: normalize + direct bf16 hi/lo split into g_aoh/g_aol ----
    const float inv0 = 1.0f / l0;
    const float inv1 = 1.0f / l1;
    const int b = bh >> 4, h = bh & 15;
#pragma unroll
    for (int j = 0; j < 8; j++) {
        const int col = h * DH_ + j * 8 + 2 * tig;
        const size_t i0 = (size_t)(b * S_ + r0a) * DM_ + col;
        const size_t i1 = (size_t)(b * S_ + r0a + 8) * DM_ + col;

        float x0 = o[j][0] * inv0, y0 = o[j][1] * inv0;
        float x1 = o[j][2] * inv1, y1 = o[j][3] * inv1;

        uint32_t h0 = pack_bf16(x0, y0);
        uint32_t h1 = pack_bf16(x1, y1);
        __nv_bfloat162 hh0 = *(__nv_bfloat162*)&h0;
        __nv_bfloat162 hh1 = *(__nv_bfloat162*)&h1;
        uint32_t l0p = pack_bf16(x0 - __bfloat162float(hh0.x),
                                 y0 - __bfloat162float(hh0.y));
        uint32_t l1p = pack_bf16(x1 - __bfloat162float(hh1.x),
                                 y1 - __bfloat162float(hh1.y));

        *(uint32_t*)&g_aoh[i0] = h0;
        *(uint32_t*)&g_aol[i0] = l0p;
        *(uint32_t*)&g_aoh[i1] = h1;
        *(uint32_t*)&g_aol[i1] = l1p;
    }
}

// ---------------- launch ----------------
extern "C" void kernel_launch(void* const* d_in, const int* in_sizes, int n_in,
                              void* d_out, int out_size)
{
    const float* x      = (const float*)d_in[0];
    const float* w_qkv  = (const float*)d_in[1];
    const float* w_o    = (const float*)d_in[2];
    const int*   tp     = (const int*)d_in[3];

    static bool attr_done = false;
    if (!attr_done) {
        cudaFuncSetAttribute(k_gemm_qkv,
            cudaFuncAttributeMaxDynamicSharedMemorySize, GEMM_SMEM_B);
        cudaFuncSetAttribute(k_gemm_out,
            cudaFuncAttributeMaxDynamicSharedMemorySize, GEMM_SMEM_B);
        attr_done = true;
    }

    // 0) one-time bf16 hi/lo splits + rope table
    k_splitg<<<(MTOK * DM_) / 1024, 256>>>(x, 0);
    k_splitg<<<(3 * DM_ * DM_) / 1024, 256>>>(w_qkv, 1);
    k_splitg<<<(DM_ * DM_) / 1024, 256>>>(w_o, 2);
    k_ropetab<<<(S_ * 32) / 256, 256>>>(tp);

    // 1) QKV projection
    k_gemm_qkv<<<dim3(3 * DM_ / 256, MTOK / 128), 256, GEMM_SMEM_B>>>();

    // 2) RoPE + bf16 hi/lo per-head layout + V transpose
    k_rope<<<(B_ * H_ * S_ * 32) / 256, 256>>>();

    // 3) causal flash attention (fused output split)
    k_attn_mma<<<dim3(S_ / 64, B_ * H_), 128>>>();

    // 4) output projection (reads g_aoh/g_aol written by attention)
    k_gemm_out<<<dim3(DM_ / 256, MTOK / 128), 256, GEMM_SMEM_B>>>((float*)d_out);
}